// round 14
// baseline (speedup 1.0000x reference)
#include <cuda_runtime.h>
#include <cuda_bf16.h>

#define CINL __device__ __forceinline__

// ------------------------- device scratch (static) -------------------------
__device__ float2 g_m1[16777216];   // [vol][64][64][32] intermediate (128 MB)
__device__ float2 g_m2[8388608];    // [vol][64][32][32]
__device__ float2 g_blk[4194304];   // [vol][jx32][jy32][jz32]
__device__ float2 g_coeffs[18432];  // [vol][s*9+l]
__device__ float2 g_coeffs2[18432];
__device__ unsigned char g_sid[32768];
__device__ float4 g_Yt4[32768*3];   // 9 Y values (+3 pad) per voxel, 16B-aligned

// ------------------------------ complex ops --------------------------------
CINL float2 cadd(float2 a,float2 b){return make_float2(a.x+b.x,a.y+b.y);}
CINL float2 csub(float2 a,float2 b){return make_float2(a.x-b.x,a.y-b.y);}
CINL float2 cmul(float2 a,float2 b){return make_float2(a.x*b.x-a.y*b.y,a.x*b.y+a.y*b.x);}

// 8-point DFT in place: out[k] = sum_n in[n] e^{SGN*2pi*i*n*k/8}
template<int SGN>
CINL void cfft8(float2 v[8]){
  const float sg=(float)SGN;
  float2 a0,a1,b0,b1,rb;
  a0=cadd(v[0],v[4]); a1=csub(v[0],v[4]); b0=cadd(v[2],v[6]); b1=csub(v[2],v[6]);
  float2 E0=cadd(a0,b0),E2=csub(a0,b0);
  rb=make_float2(-sg*b1.y,sg*b1.x);
  float2 E1=cadd(a1,rb),E3=csub(a1,rb);
  a0=cadd(v[1],v[5]); a1=csub(v[1],v[5]); b0=cadd(v[3],v[7]); b1=csub(v[3],v[7]);
  float2 O0=cadd(a0,b0),O2=csub(a0,b0);
  rb=make_float2(-sg*b1.y,sg*b1.x);
  float2 O1=cadd(a1,rb),O3=csub(a1,rb);
  const float C=0.70710678118654752f;
  float2 t1=cmul(make_float2(C,sg*C),O1);
  float2 t2=make_float2(-sg*O2.y,sg*O2.x);
  float2 t3=cmul(make_float2(-C,sg*C),O3);
  v[0]=cadd(E0,O0); v[4]=csub(E0,O0);
  v[1]=cadd(E1,t1); v[5]=csub(E1,t1);
  v[2]=cadd(E2,t2); v[6]=csub(E2,t2);
  v[3]=cadd(E3,t3); v[7]=csub(E3,t3);
}

CINL void twiddle(float2 v[8], int b, const float2* tw){
  #pragma unroll
  for(int k=1;k<8;k++) v[k]=cmul(v[k],tw[(b*k)&63]);
}

CINL void build_tw(float2* tw, float sgn){
  int t=threadIdx.x;
  if(t<64){ float s,c; __sincosf(sgn*0.09817477042468103f*(float)t,&s,&c); tw[t]=make_float2(c,s); }
}

// kept-mode index j in [0,32): forward j=k+16 (k<16) / j=k-48 (k>=48)
// j = k1 + 8*jj holds bin k = k1 + 8*K2M[jj]
#define K2M0 6
#define K2M1 7
#define K2M2 0
#define K2M3 1

// forward over a 64-long dim for 32 lines: sP[pos*33+line] (64 rows) ->
// kept 32 freqs written back to sP rows [0,32). sT: 2304 float2.
CINL void fft_fwd_tile(float2* sP, float2* sT, const float2* tw){
  int t=threadIdx.x&7, line=threadIdx.x>>3;
  float2 v[8];
  #pragma unroll
  for(int a=0;a<8;a++) v[a]=sP[(8*a+t)*33+line];
  cfft8<-1>(v); twiddle(v,t,tw);
  #pragma unroll
  for(int k=0;k<8;k++) sT[(line*8+k)*9+t]=v[k];
  __syncthreads();
  #pragma unroll
  for(int b=0;b<8;b++) v[b]=sT[(line*8+t)*9+b];
  cfft8<-1>(v);
  sP[(t+ 0)*33+line]=v[K2M0];
  sP[(t+ 8)*33+line]=v[K2M1];
  sP[(t+16)*33+line]=v[K2M2];
  sP[(t+24)*33+line]=v[K2M3];
}

// inverse: sI[j*33+line] (32 rows kept freqs) -> sO[n*33+line] (64 rows)
CINL void fft_inv_tile(const float2* sI, float2* sO, float2* sT, const float2* tw){
  int t=threadIdx.x&7, line=threadIdx.x>>3;
  float2 v[8];
  #pragma unroll
  for(int k=0;k<8;k++) v[k]=make_float2(0.f,0.f);
  v[K2M0]=sI[(t+ 0)*33+line];
  v[K2M1]=sI[(t+ 8)*33+line];
  v[K2M2]=sI[(t+16)*33+line];
  v[K2M3]=sI[(t+24)*33+line];
  cfft8<1>(v); twiddle(v,t,tw);
  #pragma unroll
  for(int k=0;k<8;k++) sT[(line*8+k)*9+t]=v[k];
  __syncthreads();
  #pragma unroll
  for(int b=0;b<8;b++) v[b]=sT[(line*8+t)*9+b];
  cfft8<1>(v);
  #pragma unroll
  for(int n2=0;n2<8;n2++) sO[(t+8*n2)*33+line]=v[n2];
}

// ----------------------- basis tables (input-independent) ------------------
__global__ void __launch_bounds__(256) k_tab(){
  int vid=blockIdx.x*256+threadIdx.x;
  if(vid>=32768) return;
  int jx=vid>>10, jy=(vid>>5)&31, jz=vid&31;
  float fx=(float)(jx-16), fy=(float)(jy-16), fz=(float)(jz-16);
  float r2=fx*fx+fy*fy+fz*fz;            // exact small integer in fp32
  float r=__fsqrt_rn(r2);                // IEEE, matches numpy bitwise
  float tt=__fdiv_rn(r,__fsqrt_rn(768.0f))*16.0f;  // *16 exact pow2
  int s=(int)tt; if(s>15)s=15;
  float Y[9];
  if(r2==0.0f){
    Y[0]=0.282095f;
    #pragma unroll
    for(int l=1;l<9;l++) Y[l]=0.f;
  }else{
    float ux=fx/r, uy=fy/r, uz=fz/r;
    Y[0]=0.282095f; Y[1]=0.488603f*uy; Y[2]=0.488603f*uz; Y[3]=0.488603f*ux;
    Y[4]=1.092548f*ux*uy; Y[5]=1.092548f*uy*uz;
    Y[6]=0.315392f*(3.0f*uz*uz-1.0f);
    Y[7]=1.092548f*ux*uz; Y[8]=0.546274f*(ux*ux-uy*uy);
  }
  g_sid[vid]=(unsigned char)s;
  g_Yt4[vid*3+0]=make_float4(Y[0],Y[1],Y[2],Y[3]);
  g_Yt4[vid*3+1]=make_float4(Y[4],Y[5],Y[6],Y[7]);
  g_Yt4[vid*3+2]=make_float4(Y[8],0.f,0.f,0.f);
}

// ---------------------------- forward FFT chain ----------------------------
// K1: z-axis (real input). block = (vol*64+x)*2 + yhalf; 32 y-lines each.
__global__ void __launch_bounds__(256) k_fwd_z(const float* __restrict__ xin){
  __shared__ float  sF[32*65];
  __shared__ float2 sT[2304];
  __shared__ float2 tw[64];
  int blk=blockIdx.x, tid=threadIdx.x;
  build_tw(tw,-1.0f);
  const float* src = xin + ((size_t)(blk>>1)<<12) + (size_t)(blk&1)*2048;
  for(int i=tid;i<2048;i+=256){ int y=i>>6, z=i&63; sF[y*65+z]=src[i]; }
  __syncthreads();
  int t=tid&7, line=tid>>3;
  float2 v[8];
  #pragma unroll
  for(int a=0;a<8;a++) v[a]=make_float2(sF[line*65+8*a+t],0.0f);
  cfft8<-1>(v); twiddle(v,t,tw);
  #pragma unroll
  for(int k=0;k<8;k++) sT[(line*8+k)*9+t]=v[k];
  __syncthreads();
  #pragma unroll
  for(int b=0;b<8;b++) v[b]=sT[(line*8+t)*9+b];
  cfft8<-1>(v);
  float2* dst = g_m1 + ((size_t)(blk>>1)<<11) + (size_t)(blk&1)*1024 + line*32;
  dst[t+ 0]=v[K2M0]; dst[t+ 8]=v[K2M1]; dst[t+16]=v[K2M2]; dst[t+24]=v[K2M3];
}

// K2: y-axis. block = vol*64 + x.
__global__ void __launch_bounds__(256) k_fwd_y(){
  __shared__ float2 sP[64*33];
  __shared__ float2 sT[2304];
  __shared__ float2 tw[64];
  int blk=blockIdx.x, tid=threadIdx.x;
  build_tw(tw,-1.0f);
  const float2* src = g_m1 + ((size_t)blk<<11);
  for(int i=tid;i<2048;i+=256) sP[(i>>5)*33+(i&31)]=src[i];
  __syncthreads();
  fft_fwd_tile(sP,sT,tw);
  __syncthreads();
  float2* dst = g_m2 + ((size_t)blk<<10);
  for(int i=tid;i<1024;i+=256) dst[i]=sP[(i>>5)*33+(i&31)];
}

// K3: x-axis. block = vol*32 + jy.
__global__ void __launch_bounds__(256) k_fwd_x(){
  __shared__ float2 sP[64*33];
  __shared__ float2 sT[2304];
  __shared__ float2 tw[64];
  int blk=blockIdx.x, tid=threadIdx.x;
  int vol=blk>>5, jy=blk&31;
  build_tw(tw,-1.0f);
  for(int i=tid;i<2048;i+=256){
    int x=i>>5, jz=i&31;
    sP[x*33+jz]=g_m2[(size_t)vol*65536 + x*1024 + jy*32 + jz];
  }
  __syncthreads();
  fft_fwd_tile(sP,sT,tw);
  __syncthreads();
  for(int i=tid;i<1024;i+=256){
    int jx=i>>5, jz=i&31;
    g_blk[(size_t)vol*32768 + jx*1024 + jy*32 + jz]=sP[jx*33+jz];
  }
}

// ---------------------- projection (masked scan, no sort) ------------------
__global__ void __launch_bounds__(256) k_proj(){
  int vol=blockIdx.x>>4, s=blockIdx.x&15;
  int tid=threadIdx.x;
  float ar[9], ai[9], cnt=0.f;
  #pragma unroll
  for(int l=0;l<9;l++){ ar[l]=0.f; ai[l]=0.f; }
  const float2* Xv = g_blk + (size_t)vol*32768;
  for(int vid=tid; vid<32768; vid+=256){
    if((int)g_sid[vid]!=s) continue;
    float2 X=Xv[vid];
    float4 y0=g_Yt4[vid*3+0], y1=g_Yt4[vid*3+1], y2=g_Yt4[vid*3+2];
    float Y[9]={y0.x,y0.y,y0.z,y0.w,y1.x,y1.y,y1.z,y1.w,y2.x};
    #pragma unroll
    for(int l=0;l<9;l++){ ar[l]+=X.x*Y[l]; ai[l]+=X.y*Y[l]; }
    cnt+=1.0f;
  }
  #pragma unroll
  for(int l=0;l<9;l++){
    for(int o=16;o;o>>=1){
      ar[l]+=__shfl_down_sync(0xffffffffu,ar[l],o);
      ai[l]+=__shfl_down_sync(0xffffffffu,ai[l],o);
    }
  }
  for(int o=16;o;o>>=1) cnt+=__shfl_down_sync(0xffffffffu,cnt,o);
  __shared__ float red[8][20];
  if((tid&31)==0){
    int w=tid>>5;
    #pragma unroll
    for(int l=0;l<9;l++){ red[w][2*l]=ar[l]; red[w][2*l+1]=ai[l]; }
    red[w][18]=cnt;
  }
  __syncthreads();
  if(tid<9){
    float vr=0.f, vi=0.f, ct=0.f;
    for(int w=0;w<8;w++){ vr+=red[w][2*tid]; vi+=red[w][2*tid+1]; ct+=red[w][18]; }
    ct=fmaxf(ct,1.0f);
    g_coeffs[(vol*16+s)*9+tid]=make_float2(__fdiv_rn(vr,ct),__fdiv_rn(vi,ct));
  }
}

// channel mixing + 1/64^3 scale. block = b*32 + co.
__global__ void __launch_bounds__(256) k_mix(const float* __restrict__ Wr,
                                             const float* __restrict__ Wi){
  int b=blockIdx.x>>5, co=blockIdx.x&31;
  int sl=threadIdx.x; if(sl>=144) return;
  float accr=0.f, acci=0.f;
  for(int ci=0;ci<32;ci++){
    float2 c=g_coeffs[(b*32+ci)*144+sl];
    float wr=Wr[(ci*32+co)*144+sl], wi=Wi[(ci*32+co)*144+sl];
    accr+=c.x*wr-c.y*wi; acci+=c.x*wi+c.y*wr;
  }
  const float sc=1.0f/262144.0f;
  g_coeffs2[(b*32+co)*144+sl]=make_float2(accr*sc,acci*sc);
}

// inverse projection: rebuild 32^3 block per output vol
__global__ void __launch_bounds__(256) k_invproj(){
  int vol=blockIdx.x, tid=threadIdx.x;
  __shared__ float2 c2[144];
  if(tid<144) c2[tid]=g_coeffs2[vol*144+tid];
  __syncthreads();
  for(int vid=tid;vid<32768;vid+=256){
    int s=g_sid[vid];
    float4 y0=g_Yt4[vid*3+0], y1=g_Yt4[vid*3+1], y2=g_Yt4[vid*3+2];
    float Y[9]={y0.x,y0.y,y0.z,y0.w,y1.x,y1.y,y1.z,y1.w,y2.x};
    const float2* cs=c2+s*9;
    float xr=0.f, xi=0.f;
    #pragma unroll
    for(int l=0;l<9;l++){ xr+=cs[l].x*Y[l]; xi+=cs[l].y*Y[l]; }
    g_blk[(size_t)vol*32768+vid]=make_float2(xr,xi);
  }
}

// ---------------------------- inverse FFT chain ----------------------------
// K7: x-axis. block = vol*32 + jy.
__global__ void __launch_bounds__(256) k_inv_x(){
  __shared__ float2 sI[32*33];
  __shared__ float2 sO[64*33];
  __shared__ float2 sT[2304];
  __shared__ float2 tw[64];
  int blk=blockIdx.x, tid=threadIdx.x;
  int vol=blk>>5, jy=blk&31;
  build_tw(tw,1.0f);
  for(int i=tid;i<1024;i+=256){
    int jx=i>>5, jz=i&31;
    sI[jx*33+jz]=g_blk[(size_t)vol*32768 + jx*1024 + jy*32 + jz];
  }
  __syncthreads();
  fft_inv_tile(sI,sO,sT,tw);
  __syncthreads();
  for(int i=tid;i<2048;i+=256){
    int x=i>>5, jz=i&31;
    g_m2[(size_t)vol*65536 + x*1024 + jy*32 + jz]=sO[x*33+jz];
  }
}

// K8: y-axis. block = vol*64 + x.
__global__ void __launch_bounds__(256) k_inv_y(){
  __shared__ float2 sI[32*33];
  __shared__ float2 sO[64*33];
  __shared__ float2 sT[2304];
  __shared__ float2 tw[64];
  int blk=blockIdx.x, tid=threadIdx.x;
  build_tw(tw,1.0f);
  const float2* src = g_m2 + ((size_t)blk<<10);
  for(int i=tid;i<1024;i+=256) sI[(i>>5)*33+(i&31)]=src[i];
  __syncthreads();
  fft_inv_tile(sI,sO,sT,tw);
  __syncthreads();
  float2* dst = g_m1 + ((size_t)blk<<11);
  for(int i=tid;i<2048;i+=256) dst[i]=sO[(i>>5)*33+(i&31)];
}

// K9: z-axis, writes output. block = (vol*64+x)*2 + yhalf; 32 y-lines.
// interleaved==1: out is complex64-style interleaved (67,108,864 floats).
// interleaved==0: out is float32 real part only (33,554,432 floats).
__global__ void __launch_bounds__(256) k_inv_z(float* __restrict__ out, int interleaved){
  __shared__ float2 sI[32*33];
  __shared__ float2 sT[2304];
  __shared__ float2 tw[64];
  int blk=blockIdx.x, tid=threadIdx.x;
  build_tw(tw,1.0f);
  const float2* src = g_m1 + ((size_t)(blk>>1)<<11) + (size_t)(blk&1)*1024;
  for(int i=tid;i<1024;i+=256) sI[(i>>5)*33+(i&31)]=src[i];
  __syncthreads();
  int t=tid&7, line=tid>>3;
  float2 v[8];
  #pragma unroll
  for(int k=0;k<8;k++) v[k]=make_float2(0.f,0.f);
  v[K2M0]=sI[line*33+t+ 0];
  v[K2M1]=sI[line*33+t+ 8];
  v[K2M2]=sI[line*33+t+16];
  v[K2M3]=sI[line*33+t+24];
  cfft8<1>(v); twiddle(v,t,tw);
  #pragma unroll
  for(int k=0;k<8;k++) sT[(line*8+k)*9+t]=v[k];
  __syncthreads();
  #pragma unroll
  for(int b=0;b<8;b++) v[b]=sT[(line*8+t)*9+b];
  cfft8<1>(v);
  size_t base = ((size_t)(blk>>1)<<12) + (size_t)(blk&1)*2048 + (size_t)line*64;
  if(interleaved){
    float2* dst = (float2*)out + base;
    #pragma unroll
    for(int n2=0;n2<8;n2++) dst[t+8*n2]=v[n2];
  }else{
    float* dst = out + base;
    #pragma unroll
    for(int n2=0;n2<8;n2++) dst[t+8*n2]=v[n2].x;
  }
}

// -------------------- fallback: zero output (contract guard) ---------------
__global__ void k_zero(float* __restrict__ out, int n){
  int i=blockIdx.x*256+threadIdx.x;
  if(i<n) out[i]=0.0f;
}

// -------------------------------- launcher ---------------------------------
extern "C" void kernel_launch(void* const* d_in, const int* in_sizes, int n_in,
                              void* d_out, int out_size){
  // Input identification (proven correct by the R12 guard experiment):
  // x = 33,554,432 elems (slot 0 or 2), W_r = slot 1, W_i = the other.
  int ix = 0;
  if (n_in >= 3 && in_sizes[2] > in_sizes[0]) ix = 2;
  int iw = 2 - ix;
  bool in_ok = (n_in >= 3)
            && in_sizes[ix] == 33554432
            && in_sizes[1]  == 147456
            && in_sizes[iw] == 147456;
  // Output interpretation: write EXACTLY out_size float32 elements.
  //   33,554,432  -> real part only (complex64 ref cast to float32 by harness)
  //   67,108,864  -> interleaved re/im (complex64 layout)
  int interleaved = -1;
  if (out_size == 33554432) interleaved = 0;
  else if (out_size == 67108864) interleaved = 1;
  if(!in_ok || interleaved < 0){
    int n = out_size;
    k_zero<<<(n+255)/256,256>>>((float*)d_out, n);
    return;
  }
  const float* x =(const float*)d_in[ix];
  const float* Wr=(const float*)d_in[1];
  const float* Wi=(const float*)d_in[iw];
  float* out=(float*)d_out;
  k_tab    <<<128,  256>>>();
  k_fwd_z  <<<16384,256>>>(x);
  k_fwd_y  <<<8192, 256>>>();
  k_fwd_x  <<<4096, 256>>>();
  k_proj   <<<2048, 256>>>();
  k_mix    <<<128,  256>>>(Wr,Wi);
  k_invproj<<<128,  256>>>();
  k_inv_x  <<<4096, 256>>>();
  k_inv_y  <<<8192, 256>>>();
  k_inv_z  <<<16384,256>>>(out, interleaved);
}

// round 15
// speedup vs baseline: 1.3026x; 1.3026x over previous
#include <cuda_runtime.h>
#include <cuda_bf16.h>

#define CINL __device__ __forceinline__

// ------------------------- device scratch (static) -------------------------
__device__ float2 g_m2[8388608];    // [vol][x64][jy32][jz32]
__device__ float2 g_blk[4194304];   // [vol][jx32][jy32][jz32]
__device__ float2 g_coeffs[18432];  // [vol][s*9+l]
__device__ float2 g_coeffs2[18432];
__device__ unsigned char g_sid[32768];
__device__ float4 g_Yt4[32768*3];   // 9 Y values (+3 pad) per voxel

// ------------------------------ complex ops --------------------------------
CINL float2 cadd(float2 a,float2 b){return make_float2(a.x+b.x,a.y+b.y);}
CINL float2 csub(float2 a,float2 b){return make_float2(a.x-b.x,a.y-b.y);}
CINL float2 cmul(float2 a,float2 b){return make_float2(a.x*b.x-a.y*b.y,a.x*b.y+a.y*b.x);}

template<int SGN>
CINL void cfft8(float2 v[8]){
  const float sg=(float)SGN;
  float2 a0,a1,b0,b1,rb;
  a0=cadd(v[0],v[4]); a1=csub(v[0],v[4]); b0=cadd(v[2],v[6]); b1=csub(v[2],v[6]);
  float2 E0=cadd(a0,b0),E2=csub(a0,b0);
  rb=make_float2(-sg*b1.y,sg*b1.x);
  float2 E1=cadd(a1,rb),E3=csub(a1,rb);
  a0=cadd(v[1],v[5]); a1=csub(v[1],v[5]); b0=cadd(v[3],v[7]); b1=csub(v[3],v[7]);
  float2 O0=cadd(a0,b0),O2=csub(a0,b0);
  rb=make_float2(-sg*b1.y,sg*b1.x);
  float2 O1=cadd(a1,rb),O3=csub(a1,rb);
  const float C=0.70710678118654752f;
  float2 t1=cmul(make_float2(C,sg*C),O1);
  float2 t2=make_float2(-sg*O2.y,sg*O2.x);
  float2 t3=cmul(make_float2(-C,sg*C),O3);
  v[0]=cadd(E0,O0); v[4]=csub(E0,O0);
  v[1]=cadd(E1,t1); v[5]=csub(E1,t1);
  v[2]=cadd(E2,t2); v[6]=csub(E2,t2);
  v[3]=cadd(E3,t3); v[7]=csub(E3,t3);
}

CINL void twiddle(float2 v[8], int b, const float2* tw){
  #pragma unroll
  for(int k=1;k<8;k++) v[k]=cmul(v[k],tw[(b*k)&63]);
}

CINL void build_tw(float2* tw, float sgn){
  int t=threadIdx.x;
  if(t<64){ float s,c; __sincosf(sgn*0.09817477042468103f*(float)t,&s,&c); tw[t]=make_float2(c,s); }
}

// kept-mode index j in [0,32): j = k1 + 8*jj holds bin k = k1 + 8*K2M[jj]
#define K2M0 6
#define K2M1 7
#define K2M2 0
#define K2M3 1

// inverse: sI[j*33+line] (32 rows kept freqs) -> sO[n*33+line] (64 rows)
CINL void fft_inv_tile(const float2* sI, float2* sO, float2* sT, const float2* tw){
  int t=threadIdx.x&7, line=threadIdx.x>>3;
  float2 v[8];
  #pragma unroll
  for(int k=0;k<8;k++) v[k]=make_float2(0.f,0.f);
  v[K2M0]=sI[(t+ 0)*33+line];
  v[K2M1]=sI[(t+ 8)*33+line];
  v[K2M2]=sI[(t+16)*33+line];
  v[K2M3]=sI[(t+24)*33+line];
  cfft8<1>(v); twiddle(v,t,tw);
  #pragma unroll
  for(int k=0;k<8;k++) sT[(line*8+k)*9+t]=v[k];
  __syncthreads();
  #pragma unroll
  for(int b=0;b<8;b++) v[b]=sT[(line*8+t)*9+b];
  cfft8<1>(v);
  #pragma unroll
  for(int n2=0;n2<8;n2++) sO[(t+8*n2)*33+line]=v[n2];
}

// ----------------------- basis tables (input-independent) ------------------
__global__ void __launch_bounds__(256) k_tab(){
  int vid=blockIdx.x*256+threadIdx.x;
  if(vid>=32768) return;
  int jx=vid>>10, jy=(vid>>5)&31, jz=vid&31;
  float fx=(float)(jx-16), fy=(float)(jy-16), fz=(float)(jz-16);
  float r2=fx*fx+fy*fy+fz*fz;
  float r=__fsqrt_rn(r2);
  float tt=__fdiv_rn(r,__fsqrt_rn(768.0f))*16.0f;
  int s=(int)tt; if(s>15)s=15;
  float Y[9];
  if(r2==0.0f){
    Y[0]=0.282095f;
    #pragma unroll
    for(int l=1;l<9;l++) Y[l]=0.f;
  }else{
    float ux=fx/r, uy=fy/r, uz=fz/r;
    Y[0]=0.282095f; Y[1]=0.488603f*uy; Y[2]=0.488603f*uz; Y[3]=0.488603f*ux;
    Y[4]=1.092548f*ux*uy; Y[5]=1.092548f*uy*uz;
    Y[6]=0.315392f*(3.0f*uz*uz-1.0f);
    Y[7]=1.092548f*ux*uz; Y[8]=0.546274f*(ux*ux-uy*uy);
  }
  g_sid[vid]=(unsigned char)s;
  g_Yt4[vid*3+0]=make_float4(Y[0],Y[1],Y[2],Y[3]);
  g_Yt4[vid*3+1]=make_float4(Y[4],Y[5],Y[6],Y[7]);
  g_Yt4[vid*3+2]=make_float4(Y[8],0.f,0.f,0.f);
}

// ---------------- K1: FUSED forward z+y FFT, per (vol, x) slab -------------
// 512 threads, dynamic smem:
//   sF: [y64][z stride65] floats        16640 B   @0
//   sG: [jz32][y stride65] float2       16640 B   @16640  (reused as [jy32][jz s33])
//   sT: 4608 float2                     36864 B   @33280
//   tw: 64 float2                         512 B   @70144   total 70656
__global__ void __launch_bounds__(512) k_fzy(const float* __restrict__ xin){
  extern __shared__ char dyn[];
  float*  sF=(float*)dyn;
  float2* sG=(float2*)(dyn+16640);
  float2* sT=(float2*)(dyn+33280);
  float2* tw=(float2*)(dyn+70144);
  int blk=blockIdx.x, tid=threadIdx.x;
  if(tid<64){ float s,c; __sincosf(-0.09817477042468103f*(float)tid,&s,&c); tw[tid]=make_float2(c,s); }
  const float* src = xin + ((size_t)blk<<12);
  for(int i=tid;i<4096;i+=512) sF[(i>>6)*65+(i&63)]=src[i];
  __syncthreads();
  int t=tid&7, line=tid>>3;          // line = y in [0,64)
  { // z-FFT over all 64 y-lines, keep 32 jz
    float2 v[8];
    #pragma unroll
    for(int a=0;a<8;a++) v[a]=make_float2(sF[line*65+8*a+t],0.f);
    cfft8<-1>(v); twiddle(v,t,tw);
    #pragma unroll
    for(int k=0;k<8;k++) sT[(line*8+k)*9+t]=v[k];
    __syncthreads();
    #pragma unroll
    for(int b=0;b<8;b++) v[b]=sT[(line*8+t)*9+b];
    cfft8<-1>(v);
    sG[(t+ 0)*65+line]=v[K2M0];
    sG[(t+ 8)*65+line]=v[K2M1];
    sG[(t+16)*65+line]=v[K2M2];
    sG[(t+24)*65+line]=v[K2M3];
  }
  __syncthreads();
  // y-FFT over 32 jz-lines (threads 0..255), keep 32 jy
  if(tid<256){
    int jz=tid>>3;
    float2 v[8];
    #pragma unroll
    for(int a=0;a<8;a++) v[a]=sG[jz*65+8*a+t];
    cfft8<-1>(v); twiddle(v,t,tw);
    #pragma unroll
    for(int k=0;k<8;k++) sT[(jz*8+k)*9+t]=v[k];
  }
  __syncthreads();   // sG fully consumed into sT
  if(tid<256){
    int jz=tid>>3;
    float2 v[8];
    #pragma unroll
    for(int b=0;b<8;b++) v[b]=sT[(jz*8+t)*9+b];
    cfft8<-1>(v);
    // reuse sG as [jy32][jz stride33]
    sG[(t+ 0)*33+jz]=v[K2M0];
    sG[(t+ 8)*33+jz]=v[K2M1];
    sG[(t+16)*33+jz]=v[K2M2];
    sG[(t+24)*33+jz]=v[K2M3];
  }
  __syncthreads();
  float2* dst = g_m2 + ((size_t)blk<<10);
  for(int i=tid;i<1024;i+=512) dst[i]=sG[(i>>5)*33+(i&31)];
}

// ---------------- K2: forward x-axis FFT. block = vol*32 + jy --------------
__global__ void __launch_bounds__(256) k_fwd_x(){
  __shared__ float2 sP[64*33];
  __shared__ float2 sT[2304];
  __shared__ float2 tw[64];
  int blk=blockIdx.x, tid=threadIdx.x;
  int vol=blk>>5, jy=blk&31;
  build_tw(tw,-1.0f);
  for(int i=tid;i<2048;i+=256){
    int x=i>>5, jz=i&31;
    sP[x*33+jz]=g_m2[(size_t)vol*65536 + x*1024 + jy*32 + jz];
  }
  __syncthreads();
  { // forward tile over x
    int t=tid&7, line=tid>>3;
    float2 v[8];
    #pragma unroll
    for(int a=0;a<8;a++) v[a]=sP[(8*a+t)*33+line];
    cfft8<-1>(v); twiddle(v,t,tw);
    #pragma unroll
    for(int k=0;k<8;k++) sT[(line*8+k)*9+t]=v[k];
    __syncthreads();
    #pragma unroll
    for(int b=0;b<8;b++) v[b]=sT[(line*8+t)*9+b];
    cfft8<-1>(v);
    sP[(t+ 0)*33+line]=v[K2M0];
    sP[(t+ 8)*33+line]=v[K2M1];
    sP[(t+16)*33+line]=v[K2M2];
    sP[(t+24)*33+line]=v[K2M3];
  }
  __syncthreads();
  for(int i=tid;i<1024;i+=256){
    int jx=i>>5, jz=i&31;
    g_blk[(size_t)vol*32768 + jx*1024 + jy*32 + jz]=sP[jx*33+jz];
  }
}

// ---------------------- projection (masked scan) ---------------------------
__global__ void __launch_bounds__(256) k_proj(){
  int vol=blockIdx.x>>4, s=blockIdx.x&15;
  int tid=threadIdx.x;
  float ar[9], ai[9], cnt=0.f;
  #pragma unroll
  for(int l=0;l<9;l++){ ar[l]=0.f; ai[l]=0.f; }
  const float2* Xv = g_blk + (size_t)vol*32768;
  for(int vid=tid; vid<32768; vid+=256){
    if((int)g_sid[vid]!=s) continue;
    float2 X=Xv[vid];
    float4 y0=g_Yt4[vid*3+0], y1=g_Yt4[vid*3+1], y2=g_Yt4[vid*3+2];
    float Y[9]={y0.x,y0.y,y0.z,y0.w,y1.x,y1.y,y1.z,y1.w,y2.x};
    #pragma unroll
    for(int l=0;l<9;l++){ ar[l]+=X.x*Y[l]; ai[l]+=X.y*Y[l]; }
    cnt+=1.0f;
  }
  #pragma unroll
  for(int l=0;l<9;l++){
    for(int o=16;o;o>>=1){
      ar[l]+=__shfl_down_sync(0xffffffffu,ar[l],o);
      ai[l]+=__shfl_down_sync(0xffffffffu,ai[l],o);
    }
  }
  for(int o=16;o;o>>=1) cnt+=__shfl_down_sync(0xffffffffu,cnt,o);
  __shared__ float red[8][20];
  if((tid&31)==0){
    int w=tid>>5;
    #pragma unroll
    for(int l=0;l<9;l++){ red[w][2*l]=ar[l]; red[w][2*l+1]=ai[l]; }
    red[w][18]=cnt;
  }
  __syncthreads();
  if(tid<9){
    float vr=0.f, vi=0.f, ct=0.f;
    for(int w=0;w<8;w++){ vr+=red[w][2*tid]; vi+=red[w][2*tid+1]; ct+=red[w][18]; }
    ct=fmaxf(ct,1.0f);
    g_coeffs[(vol*16+s)*9+tid]=make_float2(__fdiv_rn(vr,ct),__fdiv_rn(vi,ct));
  }
}

// channel mixing + 1/64^3 scale. block = b*32 + co.
__global__ void __launch_bounds__(256) k_mix(const float* __restrict__ Wr,
                                             const float* __restrict__ Wi){
  int b=blockIdx.x>>5, co=blockIdx.x&31;
  int sl=threadIdx.x; if(sl>=144) return;
  float accr=0.f, acci=0.f;
  for(int ci=0;ci<32;ci++){
    float2 c=g_coeffs[(b*32+ci)*144+sl];
    float wr=Wr[(ci*32+co)*144+sl], wi=Wi[(ci*32+co)*144+sl];
    accr+=c.x*wr-c.y*wi; acci+=c.x*wi+c.y*wr;
  }
  const float sc=1.0f/262144.0f;
  g_coeffs2[(b*32+co)*144+sl]=make_float2(accr*sc,acci*sc);
}

// --------- K5: FUSED inverse projection + inverse x FFT. blk=(vol,jy) ------
__global__ void __launch_bounds__(256) k_invx2(){
  __shared__ float2 c2[144];
  __shared__ float2 sI[32*33];
  __shared__ float2 sO[64*33];
  __shared__ float2 sT[2304];
  __shared__ float2 tw[64];
  int blk=blockIdx.x, tid=threadIdx.x;
  int vol=blk>>5, jy=blk&31;
  build_tw(tw,1.0f);
  if(tid<144) c2[tid]=g_coeffs2[vol*144+tid];
  __syncthreads();
  // rebuild X[jx][jz] for this jy from coeffs + tables
  for(int i=tid;i<1024;i+=256){
    int jx=i>>5, jz=i&31;
    int vid=jx*1024+jy*32+jz;
    int s=g_sid[vid];
    float4 y0=g_Yt4[vid*3+0], y1=g_Yt4[vid*3+1], y2=g_Yt4[vid*3+2];
    float Y[9]={y0.x,y0.y,y0.z,y0.w,y1.x,y1.y,y1.z,y1.w,y2.x};
    const float2* cs=c2+s*9;
    float xr=0.f, xi=0.f;
    #pragma unroll
    for(int l=0;l<9;l++){ xr+=cs[l].x*Y[l]; xi+=cs[l].y*Y[l]; }
    sI[jx*33+jz]=make_float2(xr,xi);
  }
  __syncthreads();
  fft_inv_tile(sI,sO,sT,tw);
  __syncthreads();
  for(int i=tid;i<2048;i+=256){
    int x=i>>5, jz=i&31;
    g_m2[(size_t)vol*65536 + x*1024 + jy*32 + jz]=sO[x*33+jz];
  }
}

// ------------- K6: FUSED inverse y+z FFT, per (vol, x) slab ----------------
// 512 threads, dynamic smem:
//   sI: [jy32][jz s33] float2    8448 B  @0
//   sG: [y64][jz s33]  float2   16896 B  @8448
//   sT: 4608 float2             36864 B  @25344
//   tw: 64 float2                 512 B  @62208   total 62720
__global__ void __launch_bounds__(512) k_izy(float* __restrict__ out, int interleaved){
  extern __shared__ char dyn[];
  float2* sI=(float2*)dyn;
  float2* sG=(float2*)(dyn+8448);
  float2* sT=(float2*)(dyn+25344);
  float2* tw=(float2*)(dyn+62208);
  int blk=blockIdx.x, tid=threadIdx.x;
  if(tid<64){ float s,c; __sincosf(0.09817477042468103f*(float)tid,&s,&c); tw[tid]=make_float2(c,s); }
  const float2* src = g_m2 + ((size_t)blk<<10);
  for(int i=tid;i<1024;i+=512) sI[(i>>5)*33+(i&31)]=src[i];
  __syncthreads();
  int t=tid&7;
  // y-inverse over 32 jz-lines (threads 0..255): jy32 -> y64
  if(tid<256){
    int jz=tid>>3;
    float2 v[8];
    #pragma unroll
    for(int k=0;k<8;k++) v[k]=make_float2(0.f,0.f);
    v[K2M0]=sI[(t+ 0)*33+jz];
    v[K2M1]=sI[(t+ 8)*33+jz];
    v[K2M2]=sI[(t+16)*33+jz];
    v[K2M3]=sI[(t+24)*33+jz];
    cfft8<1>(v); twiddle(v,t,tw);
    #pragma unroll
    for(int k=0;k<8;k++) sT[(jz*8+k)*9+t]=v[k];
  }
  __syncthreads();
  if(tid<256){
    int jz=tid>>3;
    float2 v[8];
    #pragma unroll
    for(int b=0;b<8;b++) v[b]=sT[(jz*8+t)*9+b];
    cfft8<1>(v);
    #pragma unroll
    for(int n2=0;n2<8;n2++) sG[(t+8*n2)*33+jz]=v[n2];
  }
  __syncthreads();
  // z-inverse over all 64 y-lines (512 threads): jz32 -> z64, write out
  {
    int y=tid>>3;
    float2 v[8];
    #pragma unroll
    for(int k=0;k<8;k++) v[k]=make_float2(0.f,0.f);
    v[K2M0]=sG[y*33 + t+ 0];
    v[K2M1]=sG[y*33 + t+ 8];
    v[K2M2]=sG[y*33 + t+16];
    v[K2M3]=sG[y*33 + t+24];
    cfft8<1>(v); twiddle(v,t,tw);
    #pragma unroll
    for(int k=0;k<8;k++) sT[(y*8+k)*9+t]=v[k];
    __syncthreads();
    #pragma unroll
    for(int b=0;b<8;b++) v[b]=sT[(y*8+t)*9+b];
    cfft8<1>(v);
    size_t base=((size_t)blk<<12)+(size_t)y*64;
    if(interleaved){
      float2* dst=(float2*)out + base;
      #pragma unroll
      for(int n2=0;n2<8;n2++) dst[t+8*n2]=v[n2];
    }else{
      float* dst=out+base;
      #pragma unroll
      for(int n2=0;n2<8;n2++) dst[t+8*n2]=v[n2].x;
    }
  }
}

// -------------------- fallback: zero output (contract guard) ---------------
__global__ void k_zero(float* __restrict__ out, int n){
  int i=blockIdx.x*256+threadIdx.x;
  if(i<n) out[i]=0.0f;
}

// -------------------------------- launcher ---------------------------------
extern "C" void kernel_launch(void* const* d_in, const int* in_sizes, int n_in,
                              void* d_out, int out_size){
  int ix = 0;
  if (n_in >= 3 && in_sizes[2] > in_sizes[0]) ix = 2;
  int iw = 2 - ix;
  bool in_ok = (n_in >= 3)
            && in_sizes[ix] == 33554432
            && in_sizes[1]  == 147456
            && in_sizes[iw] == 147456;
  int interleaved = -1;
  if (out_size == 33554432) interleaved = 0;
  else if (out_size == 67108864) interleaved = 1;
  if(!in_ok || interleaved < 0){
    int n = out_size;
    k_zero<<<(n+255)/256,256>>>((float*)d_out, n);
    return;
  }
  const float* x =(const float*)d_in[ix];
  const float* Wr=(const float*)d_in[1];
  const float* Wi=(const float*)d_in[iw];
  float* out=(float*)d_out;

  // opt-in to >48KB dynamic smem (idempotent; not an allocation)
  cudaFuncSetAttribute(k_fzy, cudaFuncAttributeMaxDynamicSharedMemorySize, 70656);
  cudaFuncSetAttribute(k_izy, cudaFuncAttributeMaxDynamicSharedMemorySize, 62720);

  k_tab   <<<128,  256>>>();
  k_fzy   <<<8192, 512, 70656>>>(x);
  k_fwd_x <<<4096, 256>>>();
  k_proj  <<<2048, 256>>>();
  k_mix   <<<128,  256>>>(Wr,Wi);
  k_invx2 <<<4096, 256>>>();
  k_izy   <<<8192, 512, 62720>>>(out, interleaved);
}